// round 1
// baseline (speedup 1.0000x reference)
#include <cuda_runtime.h>
#include <cuda_bf16.h>
#include <math.h>

#define NMAX 50000
#define EMAX 1600000
#define FIN  128
#define FOUT 64
#define ALPHA 0.2f

// ---------------- scratch (device globals; no allocation) ----------------
__device__ float g_h[NMAX * FOUT];       // h = input @ W
__device__ float g_hprime[NMAX * FOUT];  // segment sum accumulator
__device__ float g_hcol[NMAX];           // h . a1l  (= input . (W a1l))
__device__ float g_ha2r[NMAX];           // h . a2r
__device__ float g_pha1r[NMAX];          // p_h . (W a1r)
__device__ float g_nha2l[NMAX];          // new_h . (W a2l)
__device__ float g_ecsm[NMAX];           // edge_col_e -> ex -> softmax result
__device__ float g_segmax[NMAX];
__device__ float g_segsum[NMAX];
__device__ float g_erowsum[NMAX];
__device__ float g_einv[NMAX];
__device__ float g_edge_e[EMAX];
__device__ float g_v1[FIN], g_v2[FIN], g_v3[FIN], g_v4[FIN];

// ---------------- small vectors: v = W @ a-halves ----------------
__global__ void k_vec(const float* __restrict__ W,
                      const float* __restrict__ a1,
                      const float* __restrict__ a2) {
    int k = threadIdx.x;  // 128 threads
    float s1 = 0.f, s2 = 0.f, s3 = 0.f, s4 = 0.f;
#pragma unroll 8
    for (int j = 0; j < FOUT; j++) {
        float w = W[k * FOUT + j];
        s1 += w * a1[j];
        s2 += w * a1[FOUT + j];
        s3 += w * a2[j];
        s4 += w * a2[FOUT + j];
    }
    g_v1[k] = s1; g_v2[k] = s2; g_v3[k] = s3; g_v4[k] = s4;
}

// ---------------- zeroing (graph-replay safe reset) ----------------
__global__ void k_zero_n(int n) {
    int i = blockIdx.x * blockDim.x + threadIdx.x;
    if (i < n) {
        g_segmax[i] = 0.f;
        g_segsum[i] = 0.f;
        g_erowsum[i] = 0.f;
    }
}
__global__ void k_zero_hp(int n4) {  // n4 = N*FOUT/4
    int i = blockIdx.x * blockDim.x + threadIdx.x;
    if (i < n4) ((float4*)g_hprime)[i] = make_float4(0.f, 0.f, 0.f, 0.f);
}

// ---------------- GEMM: h = input @ W (N x 128 x 64) ----------------
// 256 threads = 8 warps; each warp computes 4 rows; W staged in smem.
__global__ void k_gemm(const float* __restrict__ X,
                       const float* __restrict__ W, int n) {
    __shared__ float Ws[FIN * FOUT];      // 32 KB
    __shared__ float Xs[32 * FIN];        // 16 KB
    int tid = threadIdx.x;
    for (int i = tid; i < FIN * FOUT / 4; i += 256)
        ((float4*)Ws)[i] = ((const float4*)W)[i];
    long row0 = (long)blockIdx.x * 32;
    int rem = n - (int)row0; if (rem > 32) rem = 32;
    const float4* xsrc = (const float4*)(X + row0 * FIN);
    for (int i = tid; i < rem * (FIN / 4); i += 256)
        ((float4*)Xs)[i] = xsrc[i];
    __syncthreads();
    int w = tid >> 5, lane = tid & 31;
    float acc[4][2] = {};
#pragma unroll 4
    for (int k = 0; k < FIN; k++) {
        float2 wv = ((const float2*)(Ws + k * FOUT))[lane];
#pragma unroll
        for (int r = 0; r < 4; r++) {
            float xk = Xs[(w * 4 + r) * FIN + k];
            acc[r][0] += xk * wv.x;
            acc[r][1] += xk * wv.y;
        }
    }
#pragma unroll
    for (int r = 0; r < 4; r++) {
        long row = row0 + w * 4 + r;
        if (row < n) {
            float2 o; o.x = acc[r][0]; o.y = acc[r][1];
            ((float2*)(g_h + row * FOUT))[lane] = o;
        }
    }
}

// ---------------- per-row dot products (matrix-vector) ----------------
// one warp per row; each lane owns one float4 of the 128-wide row
__global__ void k_dots(const float* __restrict__ X,
                       const float* __restrict__ P,
                       const float* __restrict__ NH, int n) {
    int warp = (blockIdx.x * blockDim.x + threadIdx.x) >> 5;
    int lane = threadIdx.x & 31;
    if (warp >= n) return;
    float4 xv = ((const float4*)(X + (long)warp * FIN))[lane];
    float4 pv = ((const float4*)(P + (long)warp * FIN))[lane];
    float4 nv = ((const float4*)(NH + (long)warp * FIN))[lane];
    float4 v1 = ((const float4*)g_v1)[lane];
    float4 v2 = ((const float4*)g_v2)[lane];
    float4 v3 = ((const float4*)g_v3)[lane];
    float4 v4 = ((const float4*)g_v4)[lane];
    float s_hcol = xv.x * v1.x + xv.y * v1.y + xv.z * v1.z + xv.w * v1.w;
    float s_ha2r = xv.x * v4.x + xv.y * v4.y + xv.z * v4.z + xv.w * v4.w;
    float s_pha1 = pv.x * v2.x + pv.y * v2.y + pv.z * v2.z + pv.w * v2.w;
    float s_nha2 = nv.x * v3.x + nv.y * v3.y + nv.z * v3.z + nv.w * v3.w;
#pragma unroll
    for (int o = 16; o > 0; o >>= 1) {
        s_hcol += __shfl_down_sync(0xFFFFFFFFu, s_hcol, o);
        s_ha2r += __shfl_down_sync(0xFFFFFFFFu, s_ha2r, o);
        s_pha1 += __shfl_down_sync(0xFFFFFFFFu, s_pha1, o);
        s_nha2 += __shfl_down_sync(0xFFFFFFFFu, s_nha2, o);
    }
    if (lane == 0) {
        g_hcol[warp] = s_hcol;
        g_ha2r[warp] = s_ha2r;
        g_pha1r[warp] = s_pha1;
        g_nha2l[warp] = s_nha2;
    }
}

// ---------------- column softmax passes ----------------
__global__ void k_col1(const int* __restrict__ edge_col0,
                       const int* __restrict__ row_i, int n) {
    int i = blockIdx.x * blockDim.x + threadIdx.x;
    if (i >= n) return;
    float cs = g_hcol[edge_col0[i]] + g_pha1r[i];
    float lr = cs > 0.f ? cs : ALPHA * cs;
    float e = expf(-lr);
    g_ecsm[i] = e;
    atomicMax((int*)&g_segmax[row_i[i]], __float_as_int(e));  // e > 0 always
}
__global__ void k_col2(const int* __restrict__ row_i, int n) {
    int i = blockIdx.x * blockDim.x + threadIdx.x;
    if (i >= n) return;
    float ex = expf(g_ecsm[i] - g_segmax[row_i[i]]);
    g_ecsm[i] = ex;
    atomicAdd(&g_segsum[row_i[i]], ex);
}
__global__ void k_col3(const int* __restrict__ row_i, int n) {
    int i = blockIdx.x * blockDim.x + threadIdx.x;
    if (i >= n) return;
    g_ecsm[i] = g_ecsm[i] / (g_segsum[row_i[i]] + 1e-16f);
}

// ---------------- edge scores + rowsum ----------------
__global__ void k_edge1(const int* __restrict__ edge0,
                        const int* __restrict__ edge1,
                        const int* __restrict__ row_resort, int E) {
    int e = blockIdx.x * blockDim.x + threadIdx.x;
    if (e >= E) return;
    int rr = row_resort[e];
    float rs = g_nha2l[rr] + g_ha2r[edge1[e]];
    float lr = rs > 0.f ? rs : ALPHA * rs;
    float ee = expf(-lr) * g_ecsm[rr];
    g_edge_e[e] = ee;
    atomicAdd(&g_erowsum[edge0[e]], ee);
}
__global__ void k_rowfix(int n) {
    int i = blockIdx.x * blockDim.x + threadIdx.x;
    if (i >= n) return;
    float s = g_erowsum[i];
    if (s == 0.f) s = 1.f;
    g_einv[i] = 1.f / s;
}

// ---------------- main scatter: h_prime += edge_e * h[edge1] ----------------
// 16 threads per edge, float4 gather + red.global.add.v4.f32 scatter
__global__ void k_edge2(const int* __restrict__ edge0,
                        const int* __restrict__ edge1,
                        float* __restrict__ att_out, int E, int write_att) {
    int e = (blockIdx.x * blockDim.x + threadIdx.x) >> 4;
    int t = threadIdx.x & 15;
    if (e >= E) return;
    int dst = edge0[e], src = edge1[e];
    float ee = g_edge_e[e];
    float4 hv = *(const float4*)(g_h + (long)src * FOUT + t * 4);
    float4 r;
    r.x = ee * hv.x; r.y = ee * hv.y; r.z = ee * hv.z; r.w = ee * hv.w;
    float* dp = g_hprime + (long)dst * FOUT + t * 4;
    asm volatile("red.global.add.v4.f32 [%0], {%1, %2, %3, %4};"
                 :: "l"(__cvta_generic_to_global(dp)),
                    "f"(r.x), "f"(r.y), "f"(r.z), "f"(r.w)
                 : "memory");
    if (t == 0 && write_att) att_out[e] = ee * g_einv[dst];
}

// ---------------- finalize: out = elu(h_prime / e_rowsum) ----------------
__global__ void k_final(float* __restrict__ out, int n) {
    int i4 = blockIdx.x * blockDim.x + threadIdx.x;  // one float4 each
    if (i4 >= n * (FOUT / 4)) return;
    int row = i4 >> 4;
    float inv = g_einv[row];
    float4 v = ((const float4*)g_hprime)[i4];
    v.x *= inv; v.y *= inv; v.z *= inv; v.w *= inv;
    v.x = v.x > 0.f ? v.x : expm1f(v.x);
    v.y = v.y > 0.f ? v.y : expm1f(v.y);
    v.z = v.z > 0.f ? v.z : expm1f(v.z);
    v.w = v.w > 0.f ? v.w : expm1f(v.w);
    ((float4*)out)[i4] = v;
}

// ---------------- copy edge indices to output as float ----------------
__global__ void k_edgecopy(const int* __restrict__ edge, float* __restrict__ out,
                           int n2e) {
    int i = blockIdx.x * blockDim.x + threadIdx.x;
    if (i < n2e) out[i] = (float)edge[i];
}

extern "C" void kernel_launch(void* const* d_in, const int* in_sizes, int n_in,
                              void* d_out, int out_size) {
    const float* input      = (const float*)d_in[0];
    const float* p_h        = (const float*)d_in[1];
    const float* new_h      = (const float*)d_in[2];
    const int*   edge       = (const int*)d_in[3];
    const int*   edge_col   = (const int*)d_in[4];
    const int*   row_i      = (const int*)d_in[5];
    const int*   row_resort = (const int*)d_in[6];
    const float* W          = (const float*)d_in[8];
    const float* a1         = (const float*)d_in[9];
    const float* a2         = (const float*)d_in[10];

    int N = in_sizes[0] / FIN;
    int E = in_sizes[3] / 2;
    const int* edge0 = edge;
    const int* edge1 = edge + E;
    float* out = (float*)d_out;

    long n64 = (long)N * FOUT;
    int full = (out_size >= (int)(n64 + 2L * E + E)) ? 1 : 0;
    float* out_edges = full ? out + n64 : nullptr;
    float* out_att   = full ? out + n64 + 2L * E : out;  // dummy if !full

    const int T = 256;
    // zero scratch (every call: graph replays)
    k_zero_n<<<(N + T - 1) / T, T>>>(N);
    k_zero_hp<<<((N * FOUT / 4) + T - 1) / T, T>>>(N * FOUT / 4);

    k_vec<<<1, 128>>>(W, a1, a2);
    k_gemm<<<(N + 31) / 32, 256>>>(input, W, N);
    k_dots<<<(N * 32 + T - 1) / T, T>>>(input, p_h, new_h, N);

    k_col1<<<(N + T - 1) / T, T>>>(edge_col, row_i, N);
    k_col2<<<(N + T - 1) / T, T>>>(row_i, N);
    k_col3<<<(N + T - 1) / T, T>>>(row_i, N);

    k_edge1<<<(E + T - 1) / T, T>>>(edge0, edge1, row_resort, E);
    k_rowfix<<<(N + T - 1) / T, T>>>(N);

    k_edge2<<<(E * 16 + T - 1) / T, T>>>(edge0, edge1, out_att, E, full);
    k_final<<<((N * FOUT / 4) + T - 1) / T, T>>>(out, N);
    if (full) {
        k_edgecopy<<<(2 * E + T - 1) / T, T>>>(edge, out_edges, 2 * E);
    }
}